// round 9
// baseline (speedup 1.0000x reference)
#include <cuda_runtime.h>
#include <math.h>

// Shapes fixed by setup_inputs
#define Bb 8
#define Ss 1024
#define Ee 768
#define Hh 12
#define Dd 64
#define TOK (Bb*Ss)        // 8192
#define BH  (Bb*Hh)        // 96
#define EPSf 1e-15f
#define KSPL 384           // K elements per split-k half (Ee/2)

// ---------------- static device scratch (no runtime allocs) ----------------
// GEMM partials: 6 slots = [k-half][weight] ; weight slot 0 reused for Wo.
__device__ float g_Yh[(size_t)6*TOK*Ee];
__device__ float g_AO[(size_t)TOK*Ee];          // attention output [B,S,E]
__device__ float g_Qt[(size_t)BH*Dd*Ss];        // Q clamped, [bh][d][s]
__device__ float g_Kt[(size_t)BH*Dd*Ss];        // K clamped, [bh][d][s]
__device__ float g_V [(size_t)BH*Ss*Dd];        // V, [bh][s][d]
__device__ float g_q2[BH*Ss];                   // per-head |q|^2
__device__ float g_qi[BH*Ss];                   // 1/(1-q2)
__device__ float g_k2[BH*Ss];
__device__ float g_ki[BH*Ss];
__device__ float g_xa[TOK];                     // artanh(clip(|x|))/|x|

// ---------------- packed f32x2 helpers (sm_103a FFMA2) ----------------
__device__ __forceinline__ unsigned long long pk2(float lo, float hi){
    unsigned long long r;
    asm("mov.b64 %0, {%1, %2};" : "=l"(r) : "f"(lo), "f"(hi));
    return r;
}
__device__ __forceinline__ void upk2(unsigned long long v, float& lo, float& hi){
    asm("mov.b64 {%0, %1}, %2;" : "=f"(lo), "=f"(hi) : "l"(v));
}
__device__ __forceinline__ void fma2(unsigned long long& d,
                                     unsigned long long a, unsigned long long b){
    // componentwise IEEE fp32 fma: identical rounding to scalar fmaf
    asm("fma.rn.f32x2 %0, %1, %2, %0;" : "+l"(d) : "l"(a), "l"(b));
}

// ---------------- helpers ----------------
__device__ __forceinline__ float blockReduce256(float v){
    __shared__ float buf[8];
    int lane = threadIdx.x & 31;
    int w    = threadIdx.x >> 5;
    #pragma unroll
    for (int o = 16; o; o >>= 1) v += __shfl_down_sync(0xffffffffu, v, o);
    __syncthreads();                 // protect buf across repeated calls
    if (lane == 0) buf[w] = v;
    __syncthreads();
    float r = 0.f;
    if (threadIdx.x < 8) r = buf[threadIdx.x];
    if (w == 0){
        #pragma unroll
        for (int o = 4; o; o >>= 1) r += __shfl_down_sync(0xffffffffu, r, o);
    }
    return r;                        // valid on thread 0 only
}

// ---------------- 1) row norms of hyp_linear input ----------------
__global__ void rownorm_kernel(const float* __restrict__ Xext, int useAO){
    const float* X = useAO ? g_AO : Xext;
    int row = blockIdx.x;
    const float* xr = X + (size_t)row*Ee;
    float s = 0.f;
    #pragma unroll
    for (int j = 0; j < 3; j++){
        float v = xr[threadIdx.x + 256*j];
        s = fmaf(v, v, s);
    }
    s = blockReduce256(s);
    if (threadIdx.x == 0){
        float xn = fmaxf(sqrtf(s), EPSf);
        float t  = fminf(xn, 1.f - 1e-7f);
        float at = 0.5f * logf((1.f + t) / (1.f - t));   // artanh(clip(xn))
        g_xa[row] = at / xn;
    }
}

// ---------------- GEMM inner body (shared by qkv + wo kernels) -------------
// Computes one 128x128 tile over KSPL k-elements; FFMA2 inner product.
__device__ __forceinline__ void gemm_tile_body(const float* __restrict__ Ap,
                                               const float* __restrict__ Bp,
                                               float* __restrict__ Yout,
                                               int m0, int n0, int tid){
    __shared__ float As[16][132];
    __shared__ float Bs[16][132];
    int tx = tid & 15, ty = tid >> 4;
    int r0 = tid >> 2;            // 0..63
    int kq = (tid & 3) << 2;      // 0,4,8,12

    float4 a0 = *(const float4*)&Ap[(size_t)r0*Ee + kq];
    float4 a1 = *(const float4*)&Ap[(size_t)(r0+64)*Ee + kq];
    float4 b0 = *(const float4*)&Bp[(size_t)r0*Ee + kq];
    float4 b1 = *(const float4*)&Bp[(size_t)(r0+64)*Ee + kq];

    unsigned long long acc2[8][4];          // 8 rows x (8 cols packed in 4 f32x2)
    #pragma unroll
    for (int i=0;i<8;i++)
        #pragma unroll
        for (int j=0;j<4;j++) acc2[i][j]=0ull;   // packed {0.f, 0.f}

    for (int k0 = 0; k0 < KSPL; k0 += 16){
        As[kq+0][r0]=a0.x; As[kq+1][r0]=a0.y; As[kq+2][r0]=a0.z; As[kq+3][r0]=a0.w;
        As[kq+0][r0+64]=a1.x; As[kq+1][r0+64]=a1.y; As[kq+2][r0+64]=a1.z; As[kq+3][r0+64]=a1.w;
        Bs[kq+0][r0]=b0.x; Bs[kq+1][r0]=b0.y; Bs[kq+2][r0]=b0.z; Bs[kq+3][r0]=b0.w;
        Bs[kq+0][r0+64]=b1.x; Bs[kq+1][r0+64]=b1.y; Bs[kq+2][r0+64]=b1.z; Bs[kq+3][r0+64]=b1.w;
        __syncthreads();
        if (k0 + 16 < KSPL){
            int kn = k0 + 16 + kq;
            a0 = *(const float4*)&Ap[(size_t)r0*Ee + kn];
            a1 = *(const float4*)&Ap[(size_t)(r0+64)*Ee + kn];
            b0 = *(const float4*)&Bp[(size_t)r0*Ee + kn];
            b1 = *(const float4*)&Bp[(size_t)(r0+64)*Ee + kn];
        }
        #pragma unroll
        for (int kk = 0; kk < 16; kk++){
            float4 x0 = *(float4*)&As[kk][ty*8];
            float4 x1 = *(float4*)&As[kk][ty*8+4];
            // y pairs directly from shared: LDS.128 -> two f32x2 operands, no MOVs
            ulonglong2 yA = *(ulonglong2*)&Bs[kk][tx*8];
            ulonglong2 yB = *(ulonglong2*)&Bs[kk][tx*8+4];
            unsigned long long yp[4] = { yA.x, yA.y, yB.x, yB.y };
            float xr[8] = {x0.x,x0.y,x0.z,x0.w,x1.x,x1.y,x1.z,x1.w};
            #pragma unroll
            for (int i=0;i<8;i++){
                unsigned long long xd = pk2(xr[i], xr[i]);   // broadcast, amortized x4
                #pragma unroll
                for (int j=0;j<4;j++)
                    fma2(acc2[i][j], xd, yp[j]);
            }
        }
        __syncthreads();
    }
    #pragma unroll
    for (int i=0;i<8;i++){
        float c[8];
        #pragma unroll
        for (int j=0;j<4;j++) upk2(acc2[i][j], c[2*j], c[2*j+1]);
        float* Crow = Yout + (size_t)(m0 + ty*8 + i)*Ee + n0 + tx*8;
        *(float4*)&Crow[0] = make_float4(c[0],c[1],c[2],c[3]);
        *(float4*)&Crow[4] = make_float4(c[4],c[5],c[6],c[7]);
    }
}

// ---------------- 2a) fused QKV GEMM: z = weight*2 + k-half ----------------
// Grid 6x64x6 = 2304 CTAs -> 8 waves vs 9 for three separate launches.
__global__ __launch_bounds__(256,2) void gemm_qkv(const float* __restrict__ x,
                                                  const float* __restrict__ Wq,
                                                  const float* __restrict__ Wk,
                                                  const float* __restrict__ Wv){
    int w  = blockIdx.z >> 1;
    int kh = blockIdx.z & 1;
    const float* W = (w == 0) ? Wq : (w == 1) ? Wk : Wv;
    float* Yout = g_Yh + ((size_t)kh*3 + w)*TOK*Ee;
    int n0 = blockIdx.x << 7, m0 = blockIdx.y << 7;
    gemm_tile_body(x + (size_t)m0*Ee + kh*KSPL,
                   W + (size_t)n0*Ee + kh*KSPL,
                   Yout, m0, n0, threadIdx.x);
}

// ---------------- 2b) Wo GEMM (depends on attention) -----------------------
__global__ __launch_bounds__(256,2) void gemm_wo(const float* __restrict__ Wo){
    int kh = blockIdx.z;
    float* Yout = g_Yh + (size_t)kh*3*TOK*Ee;   // weight slot 0
    int n0 = blockIdx.x << 7, m0 = blockIdx.y << 7;
    gemm_tile_body(g_AO + (size_t)m0*Ee + kh*KSPL,
                   Wo   + (size_t)n0*Ee + kh*KSPL,
                   Yout, m0, n0, threadIdx.x);
}

// ---------------- 3) mobius epilogue + layout scatter ----------------------
// Shared body; y = sum of the two split-k partials for weight slot `wslot`.
// mode 0: Q (clamp -> g_Qt, g_q2, g_qi)   mode 1: K  -> g_Kt, g_k2, g_ki
// mode 2: V -> g_V                        mode 3: final output -> outp
__device__ __forceinline__ void post_body(const float* __restrict__ bias,
                                          int mode, int wslot,
                                          float* __restrict__ outp, int tok){
    int tid = threadIdx.x;
    const float* yr  = g_Yh + ((size_t)0*3 + wslot)*TOK*Ee + (size_t)tok*Ee;
    const float* yr2 = g_Yh + ((size_t)1*3 + wslot)*TOK*Ee + (size_t)tok*Ee;

    float yv[3], bb[3];
    float s2 = 0.f, syb = 0.f, sb2 = 0.f;
    #pragma unroll
    for (int j = 0; j < 3; j++){
        int i = tid + 256*j;
        float y = yr[i] + yr2[i];
        float b_ = bias[i];
        yv[j] = y; bb[j] = b_;
        s2  = fmaf(y, y,  s2);
        syb = fmaf(y, b_, syb);
        sb2 = fmaf(b_, b_, sb2);
    }
    float r2  = blockReduce256(s2);
    float rb  = blockReduce256(syb);
    float rbb = blockReduce256(sb2);

    __shared__ float bc[2];
    if (tid == 0){
        // mobius_matvec scale: tanh(|y|/|x| * artanh(clip(|x|))) / |y|   (c=1)
        float yn    = fmaxf(sqrtf(r2), EPSf);
        float a     = g_xa[tok];
        float scale = tanhf(yn * a) / yn;
        // mobius_add(m=scale*y, b)
        float xy = scale * rb;
        float x2 = scale * scale * r2;
        float y2 = rbb;
        float den = 1.f + 2.f*xy + x2*y2 + EPSf;
        bc[0] = scale * (1.f + 2.f*xy + y2) / den;
        bc[1] = (1.f - x2) / den;
    }
    __syncthreads();
    float c0 = bc[0], c1 = bc[1];

    __shared__ float rowbuf[Ee];
    int btok = tok >> 10, spos = tok & 1023;
    #pragma unroll
    for (int j = 0; j < 3; j++){
        int i = tid + 256*j;
        float r = c0*yv[j] + c1*bb[j];
        if (mode <= 1) r = fminf(r, 1.f - 1e-5f);      // elementwise clamp for q/k
        if (mode == 3){
            outp[(size_t)tok*Ee + i] = r;
        } else {
            int h = i >> 6, d = i & 63;
            int bh = btok*Hh + h;
            if (mode == 2){
                g_V[((size_t)bh*Ss + spos)*Dd + d] = r;
            } else {
                float* dst = (mode == 0) ? g_Qt : g_Kt;
                dst[((size_t)bh*Dd + d)*Ss + spos] = r;
                rowbuf[i] = r;
            }
        }
    }
    if (mode <= 1){
        __syncthreads();
        int w = tid >> 5, lane = tid & 31;
        for (int h = w; h < Hh; h += 8){
            float v0 = rowbuf[h*64 + lane];
            float v1 = rowbuf[h*64 + 32 + lane];
            float sh = fmaf(v0, v0, v1*v1);
            #pragma unroll
            for (int o = 16; o; o >>= 1) sh += __shfl_down_sync(0xffffffffu, sh, o);
            if (lane == 0){
                int bh = btok*Hh + h;
                float* p2 = (mode == 0) ? g_q2 : g_k2;
                float* pi = (mode == 0) ? g_qi : g_ki;
                p2[bh*Ss + spos] = sh;
                pi[bh*Ss + spos] = 1.f / (1.f - sh);
            }
        }
    }
}

// fused Q/K/V epilogue: blockIdx.y = mode (0,1,2), weight slot = mode
__global__ void post_qkv(const float* __restrict__ bq,
                         const float* __restrict__ bk,
                         const float* __restrict__ bv){
    int mode = blockIdx.y;
    const float* bias = (mode == 0) ? bq : (mode == 1) ? bk : bv;
    post_body(bias, mode, mode, nullptr, blockIdx.x);
}

// final epilogue (Wo): weight slot 0, mode 3
__global__ void post_out(const float* __restrict__ bo, float* __restrict__ outp){
    post_body(bo, 3, 0, outp, blockIdx.x);
}

// ---------------- 4) attention (single pass, no exp-max) ----------------
// p_ij = t^(-1/(8*hs)),  t = 1 + u + sqrt(u^2+2u),  u = 2(q2+k2-2qk)/((1-q2)(1-k2))
// Stages 1 & 2 use packed FFMA2 (bit-identical to scalar fmaf accumulation).
// K/V tile loads are software-pipelined: next-tile LDGs issue before stage-1
// compute of the current tile, hiding DRAM/L2 latency behind ~1000 cyc of math.
#define ATTN_SMEM ((4*64*68 + 128)*4)
__global__ __launch_bounds__(256,2) void attn_kernel(const float* __restrict__ hs_arr){
    extern __shared__ float sm[];
    float* Qts = sm;                  // [64][68] (d-major)
    float* Kts = Qts + 64*68;         // [64][68] (d-major)
    float* Vs  = Kts + 64*68;         // [64][68] (k-major)
    float* Ps  = Vs  + 64*68;         // [64][68] (q-major)
    float* ks2 = Ps  + 64*68;         // [64]
    float* ksi = ks2 + 64;            // [64]

    int bh = blockIdx.y;
    int q0 = blockIdx.x << 6;
    int bq = bh / Hh, h = bh % Hh;
    int tid = threadIdx.x;
    int tx = tid & 15, ty = tid >> 4;

    float cl = -1.f / (8.f * hs_arr[h]);

    const float* KgB = g_Kt + (size_t)bh*Dd*Ss;
    const float* VgB = g_V  + (size_t)bh*Ss*Dd;

    // load Q tile: g_Qt[bh][d][q0+q] -> Qts[d][q]
    const float* Qg = g_Qt + (size_t)bh*Dd*Ss + q0;
    #pragma unroll
    for (int r = 0; r < 4; r++){
        int fidx = tid + (r << 8);
        int d = fidx >> 4, qq = (fidx & 15) << 2;
        *(float4*)&Qts[d*68 + qq] = *(const float4*)&Qg[(size_t)d*Ss + qq];
    }
    float q2r[4], qir[4];
    #pragma unroll
    for (int i = 0; i < 4; i++){
        int qi_ = bh*Ss + q0 + ty*4 + i;
        q2r[i] = g_q2[qi_];
        qir[i] = g_qi[qi_];
    }

    // ---- prologue: prefetch tile 0 into registers ----
    float4 kreg[4], vreg[4];
    float k2reg = 0.f, kireg = 0.f;
    #pragma unroll
    for (int r = 0; r < 4; r++){
        int fidx = tid + (r << 8);
        int d = fidx >> 4, cc = (fidx & 15) << 2;
        kreg[r] = *(const float4*)&KgB[(size_t)d*Ss + cc];
        vreg[r] = *(const float4*)&VgB[(size_t)(fidx >> 4)*Dd + cc];
    }
    if (tid < 64){ k2reg = g_k2[bh*Ss + tid]; kireg = g_ki[bh*Ss + tid]; }

    unsigned long long o2[4][2];      // O accum: 4 q-rows x 4 dv packed in 2 f32x2
    float den[4];
    #pragma unroll
    for (int i=0;i<4;i++){ den[i]=0.f; o2[i][0]=0ull; o2[i][1]=0ull; }

    for (int k0 = 0; k0 < Ss; k0 += 64){
        __syncthreads();   // previous stage-2 reads of Vs/Ps done
        // commit prefetched tile to smem
        #pragma unroll
        for (int r = 0; r < 4; r++){
            int fidx = tid + (r << 8);
            int d = fidx >> 4, cc = (fidx & 15) << 2;
            *(float4*)&Kts[d*68 + cc] = kreg[r];
            *(float4*)&Vs[(fidx >> 4)*68 + cc] = vreg[r];
        }
        if (tid < 64){ ks2[tid] = k2reg; ksi[tid] = kireg; }
        __syncthreads();

        // issue next tile's LDGs now; latency hidden by stage-1 + transform
        if (k0 + 64 < Ss){
            int kn = k0 + 64;
            #pragma unroll
            for (int r = 0; r < 4; r++){
                int fidx = tid + (r << 8);
                int d = fidx >> 4, cc = (fidx & 15) << 2;
                kreg[r] = *(const float4*)&KgB[(size_t)d*Ss + kn + cc];
                vreg[r] = *(const float4*)&VgB[(size_t)(kn + (fidx >> 4))*Dd + cc];
            }
            if (tid < 64){ k2reg = g_k2[bh*Ss + kn + tid]; kireg = g_ki[bh*Ss + kn + tid]; }
        }

        // stage 1: S[q][k] = sum_d Q[q][d]*K[k][d]  (packed over k-pairs)
        unsigned long long s2a[4][2];
        #pragma unroll
        for (int i=0;i<4;i++){ s2a[i][0]=0ull; s2a[i][1]=0ull; }
        #pragma unroll 8
        for (int d = 0; d < 64; d++){
            float4 qv = *(float4*)&Qts[d*68 + ty*4];
            ulonglong2 kp = *(ulonglong2*)&Kts[d*68 + tx*4];  // {k0,k1},{k2,k3}
            float qa[4] = {qv.x,qv.y,qv.z,qv.w};
            #pragma unroll
            for (int i=0;i<4;i++){
                unsigned long long qd = pk2(qa[i], qa[i]);
                fma2(s2a[i][0], qd, kp.x);
                fma2(s2a[i][1], qd, kp.y);
            }
        }
        // unpack, transform scores -> unnormalized softmax weights
        float acc[4][4];
        #pragma unroll
        for (int i=0;i<4;i++){
            upk2(s2a[i][0], acc[i][0], acc[i][1]);
            upk2(s2a[i][1], acc[i][2], acc[i][3]);
        }
        float k2l[4], kil[4];
        #pragma unroll
        for (int j=0;j<4;j++){ k2l[j]=ks2[tx*4+j]; kil[j]=ksi[tx*4+j]; }
        #pragma unroll
        for (int i=0;i<4;i++){
            #pragma unroll
            for (int j=0;j<4;j++){
                float u = 2.f*(q2r[i] + k2l[j] - 2.f*acc[i][j]) * qir[i] * kil[j];
                u = fmaxf(u, 0.f);
                float t = 1.f + u + __fsqrt_rn(fmaf(u, u, 2.f*u));
                float p = __expf(cl * __logf(t));
                acc[i][j] = p;
                den[i] += p;
            }
        }
        // stage P to smem [q][k]
        #pragma unroll
        for (int i=0;i<4;i++)
            *(float4*)&Ps[(ty*4+i)*68 + tx*4] =
                make_float4(acc[i][0],acc[i][1],acc[i][2],acc[i][3]);
        __syncthreads();

        // stage 2: O[q][dv] += sum_k P[q][k]*V[k][dv]  (packed over dv-pairs)
        #pragma unroll 4
        for (int k4 = 0; k4 < 16; k4++){
            float4 p4[4];
            ulonglong2 vp[4];
            #pragma unroll
            for (int i=0;i<4;i++) p4[i] = *(float4*)&Ps[(ty*4+i)*68 + k4*4];
            #pragma unroll
            for (int m=0;m<4;m++) vp[m] = *(ulonglong2*)&Vs[(k4*4+m)*68 + tx*4];
            #pragma unroll
            for (int i=0;i<4;i++){
                float pa[4] = {p4[i].x,p4[i].y,p4[i].z,p4[i].w};
                #pragma unroll
                for (int m=0;m<4;m++){
                    unsigned long long pd = pk2(pa[m], pa[m]);
                    fma2(o2[i][0], pd, vp[m].x);
                    fma2(o2[i][1], pd, vp[m].y);
                }
            }
        }
    }

    // reduce den across tx (16-lane groups within warp)
    #pragma unroll
    for (int off = 8; off; off >>= 1)
        #pragma unroll
        for (int i=0;i<4;i++)
            den[i] += __shfl_xor_sync(0xffffffffu, den[i], off);

    // normalize and write g_AO [B,S,E]
    #pragma unroll
    for (int i=0;i<4;i++){
        float oc[4];
        upk2(o2[i][0], oc[0], oc[1]);
        upk2(o2[i][1], oc[2], oc[3]);
        float rd = 1.f / den[i];
        float4 o = make_float4(oc[0]*rd, oc[1]*rd, oc[2]*rd, oc[3]*rd);
        size_t dst = (size_t)(bq*Ss + q0 + ty*4 + i)*Ee + h*Dd + tx*4;
        *(float4*)&g_AO[dst] = o;
    }
}

// ---------------- launch ----------------
extern "C" void kernel_launch(void* const* d_in, const int* in_sizes, int n_in,
                              void* d_out, int out_size){
    const float* x  = (const float*)d_in[0];
    const float* Wq = (const float*)d_in[1];
    const float* bq = (const float*)d_in[2];
    const float* Wk = (const float*)d_in[3];
    const float* bk = (const float*)d_in[4];
    const float* Wv = (const float*)d_in[5];
    const float* bv = (const float*)d_in[6];
    const float* Wo = (const float*)d_in[7];
    const float* bo = (const float*)d_in[8];
    const float* hs = (const float*)d_in[9];
    float* out = (float*)d_out;

    cudaFuncSetAttribute(attn_kernel, cudaFuncAttributeMaxDynamicSharedMemorySize,
                         ATTN_SMEM);

    rownorm_kernel<<<TOK, 256>>>(x, 0);
    gemm_qkv<<<dim3(6, 64, 6), 256>>>(x, Wq, Wk, Wv);
    post_qkv<<<dim3(TOK, 3), 256>>>(bq, bk, bv);

    attn_kernel<<<dim3(16, 96), 256, ATTN_SMEM>>>(hs);

    rownorm_kernel<<<TOK, 256>>>(x, 1);
    gemm_wo<<<dim3(6, 64, 2), 256>>>(Wo);
    post_out<<<TOK, 256>>>(bo, out);
}

// round 15
// speedup vs baseline: 1.0591x; 1.0591x over previous
#include <cuda_runtime.h>
#include <math.h>

// Shapes fixed by setup_inputs
#define Bb 8
#define Ss 1024
#define Ee 768
#define Hh 12
#define Dd 64
#define TOK (Bb*Ss)        // 8192
#define BH  (Bb*Hh)        // 96
#define EPSf 1e-15f
#define KSPL 384           // K elements per split-k half (Ee/2)

// ---------------- static device scratch (no runtime allocs) ----------------
// GEMM partials: 6 slots = [k-half][weight] ; weight slot 0 reused for Wo.
__device__ float g_Yh[(size_t)6*TOK*Ee];
__device__ float g_AO[(size_t)TOK*Ee];          // attention output [B,S,E]
__device__ float g_Qt[(size_t)BH*Dd*Ss];        // Q clamped, [bh][d][s]
__device__ float g_Kt[(size_t)BH*Dd*Ss];        // K clamped, [bh][d][s]
__device__ float g_V [(size_t)BH*Ss*Dd];        // V, [bh][s][d]
__device__ float g_q2[BH*Ss];                   // per-head |q|^2
__device__ float g_qi[BH*Ss];                   // 1/(1-q2)
__device__ float g_k2[BH*Ss];
__device__ float g_ki[BH*Ss];
__device__ float g_xa[TOK];                     // artanh(clip(|x|))/|x|

// ---------------- packed f32x2 helpers (sm_103a FFMA2) ----------------
__device__ __forceinline__ unsigned long long pk2(float lo, float hi){
    unsigned long long r;
    asm("mov.b64 %0, {%1, %2};" : "=l"(r) : "f"(lo), "f"(hi));
    return r;
}
__device__ __forceinline__ void upk2(unsigned long long v, float& lo, float& hi){
    asm("mov.b64 {%0, %1}, %2;" : "=f"(lo), "=f"(hi) : "l"(v));
}
__device__ __forceinline__ void fma2(unsigned long long& d,
                                     unsigned long long a, unsigned long long b){
    // componentwise IEEE fp32 fma: identical rounding to scalar fmaf
    asm("fma.rn.f32x2 %0, %1, %2, %0;" : "+l"(d) : "l"(a), "l"(b));
}

// ---------------- helpers ----------------
__device__ __forceinline__ float blockReduce256(float v){
    __shared__ float buf[8];
    int lane = threadIdx.x & 31;
    int w    = threadIdx.x >> 5;
    #pragma unroll
    for (int o = 16; o; o >>= 1) v += __shfl_down_sync(0xffffffffu, v, o);
    __syncthreads();                 // protect buf across repeated calls
    if (lane == 0) buf[w] = v;
    __syncthreads();
    float r = 0.f;
    if (threadIdx.x < 8) r = buf[threadIdx.x];
    if (w == 0){
        #pragma unroll
        for (int o = 4; o; o >>= 1) r += __shfl_down_sync(0xffffffffu, r, o);
    }
    return r;                        // valid on thread 0 only
}

// ---------------- 1) row norms of hyp_linear input ----------------
__global__ void rownorm_kernel(const float* __restrict__ Xext, int useAO){
    const float* X = useAO ? g_AO : Xext;
    int row = blockIdx.x;
    const float* xr = X + (size_t)row*Ee;
    float s = 0.f;
    #pragma unroll
    for (int j = 0; j < 3; j++){
        float v = xr[threadIdx.x + 256*j];
        s = fmaf(v, v, s);
    }
    s = blockReduce256(s);
    if (threadIdx.x == 0){
        float xn = fmaxf(sqrtf(s), EPSf);
        float t  = fminf(xn, 1.f - 1e-7f);
        float at = 0.5f * logf((1.f + t) / (1.f - t));   // artanh(clip(xn))
        g_xa[row] = at / xn;
    }
}

// ---------------- GEMM inner body (shared by qkv + wo kernels) -------------
// 128x128 tile over KSPL k-elements; FFMA2 inner product.
// B tile stored with chunk-pad swizzle: logical col c at phys 12*(c>>3)+(c&7),
// row stride 196 -> each 8-float frag is two conflict-free LDS.128.
__device__ __forceinline__ void gemm_tile_body(const float* __restrict__ Ap,
                                               const float* __restrict__ Bp,
                                               float* __restrict__ Yout,
                                               int m0, int n0, int tid){
    __shared__ float As[16][132];
    __shared__ float Bs[16][196];
    int tx = tid & 15, ty = tid >> 4;
    int r0 = tid >> 2;            // 0..63
    int kq = (tid & 3) << 2;      // 0,4,8,12
    int pc0 = 12*(r0 >> 3) + (r0 & 7);            // phys col for r0
    int pc1 = 12*((r0+64) >> 3) + (r0 & 7);       // phys col for r0+64

    float4 a0 = *(const float4*)&Ap[(size_t)r0*Ee + kq];
    float4 a1 = *(const float4*)&Ap[(size_t)(r0+64)*Ee + kq];
    float4 b0 = *(const float4*)&Bp[(size_t)r0*Ee + kq];
    float4 b1 = *(const float4*)&Bp[(size_t)(r0+64)*Ee + kq];

    unsigned long long acc2[8][4];          // 8 rows x (8 cols packed in 4 f32x2)
    #pragma unroll
    for (int i=0;i<8;i++)
        #pragma unroll
        for (int j=0;j<4;j++) acc2[i][j]=0ull;   // packed {0.f, 0.f}

    for (int k0 = 0; k0 < KSPL; k0 += 16){
        As[kq+0][r0]=a0.x; As[kq+1][r0]=a0.y; As[kq+2][r0]=a0.z; As[kq+3][r0]=a0.w;
        As[kq+0][r0+64]=a1.x; As[kq+1][r0+64]=a1.y; As[kq+2][r0+64]=a1.z; As[kq+3][r0+64]=a1.w;
        Bs[kq+0][pc0]=b0.x; Bs[kq+1][pc0]=b0.y; Bs[kq+2][pc0]=b0.z; Bs[kq+3][pc0]=b0.w;
        Bs[kq+0][pc1]=b1.x; Bs[kq+1][pc1]=b1.y; Bs[kq+2][pc1]=b1.z; Bs[kq+3][pc1]=b1.w;
        __syncthreads();
        if (k0 + 16 < KSPL){
            int kn = k0 + 16 + kq;
            a0 = *(const float4*)&Ap[(size_t)r0*Ee + kn];
            a1 = *(const float4*)&Ap[(size_t)(r0+64)*Ee + kn];
            b0 = *(const float4*)&Bp[(size_t)r0*Ee + kn];
            b1 = *(const float4*)&Bp[(size_t)(r0+64)*Ee + kn];
        }
        #pragma unroll
        for (int kk = 0; kk < 16; kk++){
            float4 x0 = *(float4*)&As[kk][ty*8];
            float4 x1 = *(float4*)&As[kk][ty*8+4];
            // swizzled B frag: phys 12*tx .. +7, two conflict-free LDS.128
            ulonglong2 yA = *(ulonglong2*)&Bs[kk][12*tx];
            ulonglong2 yB = *(ulonglong2*)&Bs[kk][12*tx+4];
            unsigned long long yp[4] = { yA.x, yA.y, yB.x, yB.y };
            float xr[8] = {x0.x,x0.y,x0.z,x0.w,x1.x,x1.y,x1.z,x1.w};
            #pragma unroll
            for (int i=0;i<8;i++){
                unsigned long long xd = pk2(xr[i], xr[i]);   // broadcast, amortized x4
                #pragma unroll
                for (int j=0;j<4;j++)
                    fma2(acc2[i][j], xd, yp[j]);
            }
        }
        __syncthreads();
    }
    #pragma unroll
    for (int i=0;i<8;i++){
        float c[8];
        #pragma unroll
        for (int j=0;j<4;j++) upk2(acc2[i][j], c[2*j], c[2*j+1]);
        float* Crow = Yout + (size_t)(m0 + ty*8 + i)*Ee + n0 + tx*8;
        *(float4*)&Crow[0] = make_float4(c[0],c[1],c[2],c[3]);
        *(float4*)&Crow[4] = make_float4(c[4],c[5],c[6],c[7]);
    }
}

// ---------------- 2a) fused QKV GEMM: z = weight*2 + k-half ----------------
__global__ __launch_bounds__(256,2) void gemm_qkv(const float* __restrict__ x,
                                                  const float* __restrict__ Wq,
                                                  const float* __restrict__ Wk,
                                                  const float* __restrict__ Wv){
    int w  = blockIdx.z >> 1;
    int kh = blockIdx.z & 1;
    const float* W = (w == 0) ? Wq : (w == 1) ? Wk : Wv;
    float* Yout = g_Yh + ((size_t)kh*3 + w)*TOK*Ee;
    int n0 = blockIdx.x << 7, m0 = blockIdx.y << 7;
    gemm_tile_body(x + (size_t)m0*Ee + kh*KSPL,
                   W + (size_t)n0*Ee + kh*KSPL,
                   Yout, m0, n0, threadIdx.x);
}

// ---------------- 2b) Wo GEMM (depends on attention) -----------------------
__global__ __launch_bounds__(256,2) void gemm_wo(const float* __restrict__ Wo){
    int kh = blockIdx.z;
    float* Yout = g_Yh + (size_t)kh*3*TOK*Ee;   // weight slot 0
    int n0 = blockIdx.x << 7, m0 = blockIdx.y << 7;
    gemm_tile_body(g_AO + (size_t)m0*Ee + kh*KSPL,
                   Wo   + (size_t)n0*Ee + kh*KSPL,
                   Yout, m0, n0, threadIdx.x);
}

// ---------------- 3) mobius epilogue + layout scatter ----------------------
// y = sum of the two split-k partials for weight slot `wslot`.
// mode 0: Q (clamp -> g_Qt, g_q2, g_qi)   mode 1: K  -> g_Kt, g_k2, g_ki
// mode 2: V -> g_V                        mode 3: final output -> outp
__device__ __forceinline__ void post_body(const float* __restrict__ bias,
                                          int mode, int wslot,
                                          float* __restrict__ outp, int tok){
    int tid = threadIdx.x;
    const float* yr  = g_Yh + ((size_t)0*3 + wslot)*TOK*Ee + (size_t)tok*Ee;
    const float* yr2 = g_Yh + ((size_t)1*3 + wslot)*TOK*Ee + (size_t)tok*Ee;

    float yv[3], bb[3];
    float s2 = 0.f, syb = 0.f, sb2 = 0.f;
    #pragma unroll
    for (int j = 0; j < 3; j++){
        int i = tid + 256*j;
        float y = yr[i] + yr2[i];
        float b_ = bias[i];
        yv[j] = y; bb[j] = b_;
        s2  = fmaf(y, y,  s2);
        syb = fmaf(y, b_, syb);
        sb2 = fmaf(b_, b_, sb2);
    }
    float r2  = blockReduce256(s2);
    float rb  = blockReduce256(syb);
    float rbb = blockReduce256(sb2);

    __shared__ float bc[2];
    if (tid == 0){
        // mobius_matvec scale: tanh(|y|/|x| * artanh(clip(|x|))) / |y|   (c=1)
        float yn    = fmaxf(sqrtf(r2), EPSf);
        float a     = g_xa[tok];
        float scale = tanhf(yn * a) / yn;
        // mobius_add(m=scale*y, b)
        float xy = scale * rb;
        float x2 = scale * scale * r2;
        float y2 = rbb;
        float den = 1.f + 2.f*xy + x2*y2 + EPSf;
        bc[0] = scale * (1.f + 2.f*xy + y2) / den;
        bc[1] = (1.f - x2) / den;
    }
    __syncthreads();
    float c0 = bc[0], c1 = bc[1];

    __shared__ float rowbuf[Ee];
    int btok = tok >> 10, spos = tok & 1023;
    #pragma unroll
    for (int j = 0; j < 3; j++){
        int i = tid + 256*j;
        float r = c0*yv[j] + c1*bb[j];
        if (mode <= 1) r = fminf(r, 1.f - 1e-5f);      // elementwise clamp for q/k
        if (mode == 3){
            outp[(size_t)tok*Ee + i] = r;
        } else {
            int h = i >> 6, d = i & 63;
            int bh = btok*Hh + h;
            if (mode == 2){
                g_V[((size_t)bh*Ss + spos)*Dd + d] = r;
            } else {
                float* dst = (mode == 0) ? g_Qt : g_Kt;
                dst[((size_t)bh*Dd + d)*Ss + spos] = r;
                rowbuf[i] = r;
            }
        }
    }
    if (mode <= 1){
        __syncthreads();
        int w = tid >> 5, lane = tid & 31;
        for (int h = w; h < Hh; h += 8){
            float v0 = rowbuf[h*64 + lane];
            float v1 = rowbuf[h*64 + 32 + lane];
            float sh = fmaf(v0, v0, v1*v1);
            #pragma unroll
            for (int o = 16; o; o >>= 1) sh += __shfl_down_sync(0xffffffffu, sh, o);
            if (lane == 0){
                int bh = btok*Hh + h;
                float* p2 = (mode == 0) ? g_q2 : g_k2;
                float* pi = (mode == 0) ? g_qi : g_ki;
                p2[bh*Ss + spos] = sh;
                pi[bh*Ss + spos] = 1.f / (1.f - sh);
            }
        }
    }
}

// fused Q/K/V epilogue: blockIdx.y = mode (0,1,2), weight slot = mode
__global__ void post_qkv(const float* __restrict__ bq,
                         const float* __restrict__ bk,
                         const float* __restrict__ bv){
    int mode = blockIdx.y;
    const float* bias = (mode == 0) ? bq : (mode == 1) ? bk : bv;
    post_body(bias, mode, mode, nullptr, blockIdx.x);
}

// final epilogue (Wo): weight slot 0, mode 3
__global__ void post_out(const float* __restrict__ bo, float* __restrict__ outp){
    post_body(bo, 3, 0, outp, blockIdx.x);
}

// ---------------- 4) attention (single pass, no exp-max) ----------------
// p_ij = t^(-1/(8*hs)),  t = 1 + u + sqrt(u^2+2u),  u = 2(q2+k2-2qk)/((1-q2)(1-k2))
// 128q x 64k tiles, 8q x 4k per thread (FFMA2). 2 CTAs/SM, ~102KB smem.
// Crossbar demand 1.5 B/FMA (was 2.0) -> predicted ~570us.
#define ATTN_SMEM ((64*132 + 64*68 + 64*68 + 128*68 + 128)*4)
__global__ __launch_bounds__(256,2) void attn_kernel(const float* __restrict__ hs_arr){
    extern __shared__ float sm[];
    float* Qts = sm;                    // [64][132] d-major, 128 q wide
    float* Kts = Qts + 64*132;          // [64][68]  d-major, 64 k wide
    float* Vs  = Kts + 64*68;           // [64][68]  k-major, 64 dv wide
    float* Ps  = Vs  + 64*68;           // [128][68] q-major, 64 k wide
    float* ks2 = Ps  + 128*68;          // [64]
    float* ksi = ks2 + 64;              // [64]

    int bh = blockIdx.y;
    int q0 = blockIdx.x << 7;           // 128-row q block
    int bq = bh / Hh, h = bh % Hh;
    int tid = threadIdx.x;
    int tx = tid & 15, ty = tid >> 4;

    float cl = -1.f / (8.f * hs_arr[h]);

    const float* QgB = g_Qt + (size_t)bh*Dd*Ss;
    const float* KgB = g_Kt + (size_t)bh*Dd*Ss;
    const float* VgB = g_V  + (size_t)bh*Ss*Dd;

    // Q tile: 64 d x 128 q -> 8 float4 per thread
    #pragma unroll
    for (int r = 0; r < 8; r++){
        int fidx = tid + (r << 8);
        int d = fidx >> 5, qq = (fidx & 31) << 2;
        *(float4*)&Qts[d*132 + qq] = *(const float4*)&QgB[(size_t)d*Ss + q0 + qq];
    }
    float q2r[8], qir[8];
    #pragma unroll
    for (int i = 0; i < 8; i++){
        int qi_ = bh*Ss + q0 + ty*8 + i;
        q2r[i] = g_q2[qi_];
        qir[i] = g_qi[qi_];
    }

    unsigned long long o2[8][2];        // O accum: 8 q-rows x 4 dv in 2 f32x2
    float den[8];
    #pragma unroll
    for (int i=0;i<8;i++){ den[i]=0.f; o2[i][0]=0ull; o2[i][1]=0ull; }

    for (int k0 = 0; k0 < Ss; k0 += 64){
        __syncthreads();                // prior stage-2 reads of Vs/Ps done
        // K tile 64d x 64k, V tile 64k x 64dv: 4 float4 each per thread
        #pragma unroll
        for (int r = 0; r < 4; r++){
            int fidx = tid + (r << 8);
            int dr = fidx >> 4, cc = (fidx & 15) << 2;
            *(float4*)&Kts[dr*68 + cc] = *(const float4*)&KgB[(size_t)dr*Ss + k0 + cc];
            *(float4*)&Vs[dr*68 + cc]  = *(const float4*)&VgB[(size_t)(k0 + dr)*Dd + cc];
        }
        if (tid < 64){
            ks2[tid] = g_k2[bh*Ss + k0 + tid];
            ksi[tid] = g_ki[bh*Ss + k0 + tid];
        }
        __syncthreads();

        // stage 1: S[8q][4k] = sum_d Q[q][d]*K[k][d]
        unsigned long long s2a[8][2];
        #pragma unroll
        for (int i=0;i<8;i++){ s2a[i][0]=0ull; s2a[i][1]=0ull; }
        #pragma unroll 4
        for (int d = 0; d < 64; d++){
            float4 qv0 = *(float4*)&Qts[d*132 + ty*8];
            float4 qv1 = *(float4*)&Qts[d*132 + ty*8 + 4];
            ulonglong2 kp = *(ulonglong2*)&Kts[d*68 + tx*4];   // {k0,k1},{k2,k3}
            float qa[8] = {qv0.x,qv0.y,qv0.z,qv0.w,qv1.x,qv1.y,qv1.z,qv1.w};
            #pragma unroll
            for (int i=0;i<8;i++){
                unsigned long long qd = pk2(qa[i], qa[i]);
                fma2(s2a[i][0], qd, kp.x);
                fma2(s2a[i][1], qd, kp.y);
            }
        }
        // transform scores -> unnormalized softmax weights
        float acc[8][4];
        #pragma unroll
        for (int i=0;i<8;i++){
            upk2(s2a[i][0], acc[i][0], acc[i][1]);
            upk2(s2a[i][1], acc[i][2], acc[i][3]);
        }
        float k2l[4], kil[4];
        #pragma unroll
        for (int j=0;j<4;j++){ k2l[j]=ks2[tx*4+j]; kil[j]=ksi[tx*4+j]; }
        #pragma unroll
        for (int i=0;i<8;i++){
            #pragma unroll
            for (int j=0;j<4;j++){
                float u = 2.f*(q2r[i] + k2l[j] - 2.f*acc[i][j]) * qir[i] * kil[j];
                u = fmaxf(u, 0.f);
                float t = 1.f + u + __fsqrt_rn(fmaf(u, u, 2.f*u));
                float p = __expf(cl * __logf(t));
                acc[i][j] = p;
                den[i] += p;
            }
        }
        // stage P to smem [q][k]
        #pragma unroll
        for (int i=0;i<8;i++)
            *(float4*)&Ps[(ty*8+i)*68 + tx*4] =
                make_float4(acc[i][0],acc[i][1],acc[i][2],acc[i][3]);
        __syncthreads();

        // stage 2: O[8q][4dv] += sum_k P[q][k]*V[k][dv]
        #pragma unroll 2
        for (int k4 = 0; k4 < 16; k4++){
            ulonglong2 vp[4];
            #pragma unroll
            for (int m=0;m<4;m++) vp[m] = *(ulonglong2*)&Vs[(k4*4+m)*68 + tx*4];
            #pragma unroll
            for (int i=0;i<8;i++){
                float4 p4 = *(float4*)&Ps[(ty*8+i)*68 + k4*4];
                float pa[4] = {p4.x,p4.y,p4.z,p4.w};
                #pragma unroll
                for (int m=0;m<4;m++){
                    unsigned long long pd = pk2(pa[m], pa[m]);
                    fma2(o2[i][0], pd, vp[m].x);
                    fma2(o2[i][1], pd, vp[m].y);
                }
            }
        }
    }

    // reduce den across tx (16-lane groups within warp)
    #pragma unroll
    for (int off = 8; off; off >>= 1)
        #pragma unroll
        for (int i=0;i<8;i++)
            den[i] += __shfl_xor_sync(0xffffffffu, den[i], off);

    // normalize and write g_AO [B,S,E]
    #pragma unroll
    for (int i=0;i<8;i++){
        float oc[4];
        upk2(o2[i][0], oc[0], oc[1]);
        upk2(o2[i][1], oc[2], oc[3]);
        float rd = 1.f / den[i];
        float4 o = make_float4(oc[0]*rd, oc[1]*rd, oc[2]*rd, oc[3]*rd);
        size_t dst = (size_t)(bq*Ss + q0 + ty*8 + i)*Ee + h*Dd + tx*4;
        *(float4*)&g_AO[dst] = o;
    }
}

// ---------------- launch ----------------
extern "C" void kernel_launch(void* const* d_in, const int* in_sizes, int n_in,
                              void* d_out, int out_size){
    const float* x  = (const float*)d_in[0];
    const float* Wq = (const float*)d_in[1];
    const float* bq = (const float*)d_in[2];
    const float* Wk = (const float*)d_in[3];
    const float* bk = (const float*)d_in[4];
    const float* Wv = (const float*)d_in[5];
    const float* bv = (const float*)d_in[6];
    const float* Wo = (const float*)d_in[7];
    const float* bo = (const float*)d_in[8];
    const float* hs = (const float*)d_in[9];
    float* out = (float*)d_out;

    cudaFuncSetAttribute(attn_kernel, cudaFuncAttributeMaxDynamicSharedMemorySize,
                         ATTN_SMEM);

    rownorm_kernel<<<TOK, 256>>>(x, 0);
    gemm_qkv<<<dim3(6, 64, 6), 256>>>(x, Wq, Wk, Wv);
    post_qkv<<<dim3(TOK, 3), 256>>>(bq, bk, bv);

    attn_kernel<<<dim3(8, 96), 256, ATTN_SMEM>>>(hs);

    rownorm_kernel<<<TOK, 256>>>(x, 1);
    gemm_wo<<<dim3(6, 64, 2), 256>>>(Wo);
    post_out<<<TOK, 256>>>(bo, out);
}